// round 7
// baseline (speedup 1.0000x reference)
#include <cuda_runtime.h>
#include <cuda_bf16.h>

// VQLayer forward == identity copy of `inputs`.
//   quantized = closest + stop_gradient(inputs - closest) == inputs (forward value;
//   stop_gradient is identity in the forward pass, so the whole distance/argmin/
//   gather pipeline cancels algebraically). Verified: rel_err 1.1e-8.
//
// R1-R3 established the floor: 2048-blk kernel (6.59us), 512-blk MLP4 kernel
// (6.66us), driver memcpy node (6.88us) -- three unrelated mechanisms within
// noise of each other while no pipe exceeds 18%. The wall clock is a per-replay
// floor (short-burst DVFS clocks + replay overhead), not a kernel property.
//
// Final form: best-measured shape (2048x256, one float4/thread), DEFAULT cache
// ops so steady-state replays hit the 126MB L2 (both buffers fit; streaming
// hints in R2 forced evict-first and gave nothing). Traffic is irreducible:
// 8 MB read + 8 MB write.

__global__ void __launch_bounds__(256)
vq_identity_copy_kernel(const float4* __restrict__ in,
                        float4* __restrict__ out) {
    int i = blockIdx.x * 256 + threadIdx.x;
    out[i] = in[i];
}

// Fallback for sizes not divisible by 1024 bytes (not expected for this problem).
__global__ void vq_copy_gs_kernel(const float4* __restrict__ in,
                                  float4* __restrict__ out, int n4) {
    int i = blockIdx.x * blockDim.x + threadIdx.x;
    for (; i < n4; i += gridDim.x * blockDim.x)
        out[i] = in[i];
}

extern "C" void kernel_launch(void* const* d_in, const int* in_sizes, int n_in,
                              void* d_out, int out_size) {
    const float4* in = (const float4*)d_in[0];
    float4* out = (float4*)d_out;

    int n4 = out_size / 4;  // 524288 expected (2097152 floats / 4)
    if ((out_size & 3) == 0 && (n4 & 255) == 0) {
        vq_identity_copy_kernel<<<n4 / 256, 256>>>(in, out);  // 2048 blocks
    } else {
        vq_copy_gs_kernel<<<(n4 + 255) / 256, 256>>>(in, out, n4);
    }
}